// round 15
// baseline (speedup 1.0000x reference)
#include <cuda_runtime.h>
#include <cuda_fp16.h>
#include <math.h>
#include <stdint.h>

// ---------------- problem constants ----------------
#define BB     2
#define SEQ    2048
#define DMODEL 2048
#define HKN    16
#define HVN    32
#define DKD    128
#define DVD    128
#define KDIM   2048
#define VDIM   4096
#define CONVD  8192
#define BSTOK  (BB*SEQ)
#define CT     64
#define NCH    (SEQ/CT)

// ---------------- scratch ----------------
__device__ float  g_mixed[(size_t)BSTOK * CONVD];
__device__ float  g_z    [(size_t)BSTOK * VDIM];
__device__ float  g_q    [(size_t)BSTOK * KDIM];
__device__ float  g_k    [(size_t)BSTOK * KDIM];
__device__ float  g_v    [(size_t)BSTOK * VDIM];
__device__ float  g_g    [(size_t)BSTOK * HVN];   // raw g
__device__ float  g_beta [(size_t)BSTOK * HVN];
__device__ float  g_core [(size_t)BSTOK * VDIM];
__device__ __half g_xh   [(size_t)BSTOK * DMODEL];
__device__ __half g_wqkvh[(size_t)CONVD * DMODEL];
__device__ __half g_wzh  [(size_t)VDIM * DMODEL];
__device__ __half g_wouth[(size_t)DMODEL * VDIM];
__device__ __half g_coreh[(size_t)BSTOK * VDIM];

// ---------------- ptx helpers ----------------
__device__ __forceinline__ uint32_t smem_u32(const void* p) {
    return (uint32_t)__cvta_generic_to_shared(p);
}
__device__ __forceinline__ void cp16(uint32_t saddr, const void* g) {
    asm volatile("cp.async.cg.shared.global [%0], [%1], 16;\n" :: "r"(saddr), "l"(g));
}
__device__ __forceinline__ void cp_commit() { asm volatile("cp.async.commit_group;\n"); }
template<int N> __device__ __forceinline__ void cp_wait() {
    asm volatile("cp.async.wait_group %0;\n" :: "n"(N));
}
__device__ __forceinline__ void ldsm_x4(uint32_t* r, uint32_t addr) {
    asm volatile("ldmatrix.sync.aligned.m8n8.x4.shared.b16 {%0,%1,%2,%3}, [%4];"
                 : "=r"(r[0]), "=r"(r[1]), "=r"(r[2]), "=r"(r[3]) : "r"(addr));
}
__device__ __forceinline__ void mma16816(float* c, const uint32_t* a, const uint32_t* b) {
    asm volatile(
        "mma.sync.aligned.m16n8k16.row.col.f32.f16.f16.f32 "
        "{%0,%1,%2,%3}, {%4,%5,%6,%7}, {%8,%9}, {%0,%1,%2,%3};"
        : "+f"(c[0]), "+f"(c[1]), "+f"(c[2]), "+f"(c[3])
        : "r"(a[0]), "r"(a[1]), "r"(a[2]), "r"(a[3]), "r"(b[0]), "r"(b[1]));
}
// packed fp32x2
typedef unsigned long long ull;
__device__ __forceinline__ ull f2fma(ull a, ull b, ull c) {
    ull d;
    asm("fma.rn.f32x2 %0, %1, %2, %3;" : "=l"(d) : "l"(a), "l"(b), "l"(c));
    return d;
}
__device__ __forceinline__ ull f2mul(ull a, ull b) {
    ull d;
    asm("mul.rn.f32x2 %0, %1, %2;" : "=l"(d) : "l"(a), "l"(b));
    return d;
}
__device__ __forceinline__ ull pack2(float x, float y) {
    ull r;
    asm("mov.b64 %0, {%1, %2};" : "=l"(r) : "r"(__float_as_uint(x)), "r"(__float_as_uint(y)));
    return r;
}
__device__ __forceinline__ float hsum2(ull v) {
    uint32_t lo, hi;
    asm("mov.b64 {%0, %1}, %2;" : "=r"(lo), "=r"(hi) : "l"(v));
    return __uint_as_float(lo) + __uint_as_float(hi);
}
__device__ __forceinline__ void unpack2(ull v, float& lo, float& hi) {
    uint32_t l, h;
    asm("mov.b64 {%0, %1}, %2;" : "=r"(l), "=r"(h) : "l"(v));
    lo = __uint_as_float(l); hi = __uint_as_float(h);
}

// =====================================================================
// fp16 GEMM (proven, 416 TF/s measured). Do not touch.
// =====================================================================
#define NSTAGE 4
#define A_STAGE_BYTES 16384
#define B_STAGE_BYTES 32768
#define STAGE_BYTES   (A_STAGE_BYTES + B_STAGE_BYTES)
#define GEMM_DYN (NSTAGE*STAGE_BYTES + 1024)

__global__ __launch_bounds__(256, 1) void gemm_fp16(
    const __half* __restrict__ A, const __half* __restrict__ Bt,
    float* __restrict__ C, int M, int N, int K)
{
    extern __shared__ __align__(16) uint8_t dyn[];
    const uint32_t dynb = smem_u32(dyn);
    const uint32_t base = (dynb + 1023u) & ~1023u;

    const int tid  = threadIdx.x;
    const int wid  = tid >> 5;
    const int lane = tid & 31;
    const int bm0 = blockIdx.y * 128;
    const int bn0 = blockIdx.x * 256;
    const int wm  = (wid & 1) * 64;
    const int wn  = (wid >> 1) * 64;
    const int KT  = K >> 6;

    const __half* Arow = A  + (size_t)bm0 * K;
    const __half* Brow = Bt + (size_t)bn0 * K;

    auto load_tile = [&](int buf, int kt) {
        const uint32_t ab = base + buf * STAGE_BYTES;
        const uint32_t bb = ab + A_STAGE_BYTES;
        const int k0 = kt << 6;
        #pragma unroll
        for (int t = 0; t < 4; t++) {
            int c = tid + t * 256;
            int row = c >> 3;
            int cb  = (c & 7) << 4;
            uint32_t off = (uint32_t)(row * 128 + cb);
            uint32_t sw = off ^ ((off >> 3) & 0x70u);
            cp16(ab + sw, Arow + (size_t)row * K + k0 + (cb >> 1));
        }
        #pragma unroll
        for (int t = 0; t < 8; t++) {
            int c = tid + t * 256;
            int row = c >> 3;
            int cb  = (c & 7) << 4;
            uint32_t off = (uint32_t)(row * 128 + cb);
            uint32_t sw = off ^ ((off >> 3) & 0x70u);
            cp16(bb + sw, Brow + (size_t)row * K + k0 + (cb >> 1));
        }
        cp_commit();
    };

    const int aRowL = lane & 15;
    const int aKH2  = (lane >> 4) * 16;
    const int bRowL = ((lane >> 4) & 1) * 8 + (lane & 7);
    const int bKH2  = ((lane >> 3) & 1) * 16;

    float acc[4][8][4];
    #pragma unroll
    for (int i = 0; i < 4; i++)
        #pragma unroll
        for (int j = 0; j < 8; j++)
            #pragma unroll
            for (int q = 0; q < 4; q++) acc[i][j][q] = 0.0f;

    load_tile(0, 0);
    load_tile(1, KT > 1 ? 1 : 0);
    load_tile(2, KT > 2 ? 2 : 0);

    for (int i = 0; i < KT; i++) {
        cp_wait<2>();
        __syncthreads();

        if (i + 3 < KT) load_tile((i + 3) % NSTAGE, i + 3);
        else            cp_commit();

        const uint32_t ab = base + (i % NSTAGE) * STAGE_BYTES;
        const uint32_t bb = ab + A_STAGE_BYTES;

        #pragma unroll
        for (int ks = 0; ks < 4; ks++) {
            uint32_t af[4][4];
            uint32_t bf[4][4];
            #pragma unroll
            for (int mi = 0; mi < 4; mi++) {
                int row = wm + mi * 16 + aRowL;
                uint32_t cb = (uint32_t)((ks * 32 + aKH2) ^ ((row & 7) << 4));
                ldsm_x4(af[mi], ab + row * 128 + cb);
            }
            #pragma unroll
            for (int ni2 = 0; ni2 < 4; ni2++) {
                int row = wn + ni2 * 16 + bRowL;
                uint32_t cb = (uint32_t)((ks * 32 + bKH2) ^ ((row & 7) << 4));
                ldsm_x4(bf[ni2], bb + row * 128 + cb);
            }
            #pragma unroll
            for (int mi = 0; mi < 4; mi++)
                #pragma unroll
                for (int ni = 0; ni < 8; ni++)
                    mma16816(acc[mi][ni], af[mi], &bf[ni >> 1][(ni & 1) * 2]);
        }
    }

    const int l4 = lane >> 2;
    const int l2 = (lane & 3) * 2;
    #pragma unroll
    for (int mi = 0; mi < 4; mi++) {
        #pragma unroll
        for (int ni = 0; ni < 8; ni++) {
            float* c = acc[mi][ni];
            size_t r = (size_t)(bm0 + wm + mi * 16 + l4) * N + bn0 + wn + ni * 8 + l2;
            *(float2*)(C + r)                 = make_float2(c[0], c[1]);
            *(float2*)(C + r + 8 * (size_t)N) = make_float2(c[2], c[3]);
        }
    }
}

// =====================================================================
// prep kernels
// =====================================================================
__global__ __launch_bounds__(256) void round_f16_kernel(
    const float* __restrict__ src, __half* __restrict__ dst, int n4)
{
    int i = blockIdx.x * 256 + threadIdx.x;
    if (i < n4) {
        float4 v = ((const float4*)src)[i];
        ((__half2*)dst)[i * 2]     = __floats2half2_rn(v.x, v.y);
        ((__half2*)dst)[i * 2 + 1] = __floats2half2_rn(v.z, v.w);
    }
}

__global__ __launch_bounds__(256) void transpose_f16(
    const float* __restrict__ src, __half* __restrict__ dst, int K, int N)
{
    __shared__ float tile[32][33];
    const int n0 = blockIdx.x * 32, k0 = blockIdx.y * 32;
    const int tx = threadIdx.x & 31, ty = threadIdx.x >> 5;
    #pragma unroll
    for (int j = 0; j < 32; j += 8)
        tile[ty + j][tx] = src[(size_t)(k0 + ty + j) * N + n0 + tx];
    __syncthreads();
    #pragma unroll
    for (int j = 0; j < 32; j += 8)
        dst[(size_t)(n0 + ty + j) * K + k0 + tx] = __float2half_rn(tile[tx][ty + j]);
}

// =====================================================================
// b/a projections -> beta, g (raw log-decay)
// =====================================================================
__global__ __launch_bounds__(256) void proj_ba_kernel(
    const float* __restrict__ X, const float* __restrict__ wb,
    const float* __restrict__ wa, const float* __restrict__ dt_bias,
    const float* __restrict__ A_log,
    float* __restrict__ beta, float* __restrict__ gout)
{
    __shared__ float xs[DMODEL];
    const int bs = blockIdx.x;
    const int tid = threadIdx.x;
    for (int t = tid; t < DMODEL; t += 256)
        xs[t] = X[(size_t)bs * DMODEL + t];
    __syncthreads();

    const int out  = tid >> 2;
    const int part = tid & 3;
    const bool is_b = (out < 32);
    const int h = is_b ? out : out - 32;
    const float* w = (is_b ? wb : wa) + h;

    float acc = 0.0f;
    #pragma unroll 8
    for (int d = part; d < DMODEL; d += 4)
        acc += xs[d] * w[d * 32];
    acc += __shfl_xor_sync(0xffffffffu, acc, 1);
    acc += __shfl_xor_sync(0xffffffffu, acc, 2);

    if (part == 0) {
        if (is_b) {
            beta[(size_t)bs * HVN + h] = 1.0f / (1.0f + expf(-acc));
        } else {
            float x = acc + dt_bias[h];
            float sp = (x > 20.0f) ? x : log1pf(expf(x));
            gout[(size_t)bs * HVN + h] = -expf(A_log[h]) * sp;
        }
    }
}

// =====================================================================
// conv1d(K=4) + silu + per-head l2norm for q,k. One CTA per token.
// =====================================================================
__global__ __launch_bounds__(256) void conv_qk_kernel(const float* __restrict__ conv_w)
{
    const int bs   = blockIdx.x;
    const int s    = bs % SEQ;
    const long bsl = bs;
    const int half = threadIdx.x >> 7;
    const int lane = threadIdx.x & 127;
    __shared__ float red[2][4];

    #pragma unroll 1
    for (int it = 0; it < 16; it++) {
        const int hy = it * 2 + half;
        const bool is_k = (hy >= HKN);
        const int head  = is_k ? hy - HKN : hy;
        const int c     = (is_k ? KDIM : 0) + head * DKD + lane;

        const float4 w4 = *(const float4*)(conv_w + c * 4);

        float acc = w4.w * g_mixed[bsl * CONVD + c];
        if (s > 0) acc += w4.z * g_mixed[(bsl - 1) * CONVD + c];
        if (s > 1) acc += w4.y * g_mixed[(bsl - 2) * CONVD + c];
        if (s > 2) acc += w4.x * g_mixed[(bsl - 3) * CONVD + c];

        float val = acc / (1.0f + expf(-acc));

        float ss2 = val * val;
        #pragma unroll
        for (int o = 16; o > 0; o >>= 1)
            ss2 += __shfl_xor_sync(0xffffffffu, ss2, o);
        if ((lane & 31) == 0) red[half][lane >> 5] = ss2;
        __syncthreads();
        float tot = red[half][0] + red[half][1] + red[half][2] + red[half][3];

        float outv = val * rsqrtf(tot + 1e-6f);
        if (!is_k) outv *= 0.08838834764831845f;

        float* dst = is_k ? g_k : g_q;
        dst[(size_t)bs * KDIM + head * DKD + lane] = outv;
        __syncthreads();
    }
}

// =====================================================================
// conv1d + silu for v. Grid-stride, 2048 CTAs.
// =====================================================================
__global__ __launch_bounds__(256) void conv_v_kernel(const float* __restrict__ conv_w)
{
    const size_t total = (size_t)BSTOK * VDIM;
    for (size_t idx = (size_t)blockIdx.x * 256 + threadIdx.x; idx < total;
         idx += (size_t)gridDim.x * 256) {
        const int cv = (int)(idx % VDIM);
        const long bsl = (long)(idx / VDIM);
        const int s = (int)(bsl % SEQ);
        const int c = 2 * KDIM + cv;

        const float4 w4 = *(const float4*)(conv_w + c * 4);

        float acc = w4.w * g_mixed[bsl * CONVD + c];
        if (s > 0) acc += w4.z * g_mixed[(bsl - 1) * CONVD + c];
        if (s > 1) acc += w4.y * g_mixed[(bsl - 2) * CONVD + c];
        if (s > 2) acc += w4.x * g_mixed[(bsl - 3) * CONVD + c];

        g_v[idx] = acc / (1.0f + expf(-acc));
    }
}

// =====================================================================
// CHUNKED gated delta-rule scan (WY form) — atomic-free version.
// vs r14 (passed): the k.S0/q.S0 partial-dot combine now uses a quad
// layout (col2 = tid>>2, ks2 = tid&3) with INTERLEAVED dim-pairs
// (pair p -> ull index 4p+ks2, conflict-free 32B quad groups) and
// 2x shfl_xor + single STS instead of smem atomicAdd. The state
// registers are relabeled accordingly (same sums). Output loop is
// balanced: group ks takes t == ks (mod 4).
// =====================================================================
#define KSJ_STRIDE 66
#define SCAN_SMEM_FLOATS (8192 + 8192 + 128*KSJ_STRIDE + 4096*4 + 256)
#define SCAN_SMEM (SCAN_SMEM_FLOATS * 4)

__global__ __launch_bounds__(256, 1) void scan_kernel()
{
    extern __shared__ __align__(16) float sm[];
    float* Ks  = sm;                       // [64][128]
    float* Qs  = Ks + 8192;                // [64][128]
    float* Ksj = Qs + 8192;                // [128][KSJ_STRIDE]
    float* Vs  = Ksj + 128 * KSJ_STRIDE;   // [64][64]
    float* Am  = Vs + 4096;                // [64][64]
    float* Dl  = Am + 4096;                // [64][64]
    float* Ot  = Dl + 4096;                // [64][64]
    float* cg  = Ot + 4096;                // [64]
    float* bet = cg + 64;
    float* gam = bet + 64;
    float* wT  = gam + 64;

    const int blk  = blockIdx.x;
    const int half = blk & 1;
    const int hv   = (blk >> 1) & (HVN - 1);
    const int b    = blk >> 6;
    const int kh   = hv >> 1;
    const int tid  = threadIdx.x;
    const int col  = tid & 63;          // for A/B/subst/outputs
    const int ks   = tid >> 6;          // 0..3 (group)
    const int tb   = tid >> 4;          // A/B tile row
    const int jb   = tid & 15;          // A/B tile col
    const int col2 = tid >> 2;          // state-owning column (0..63)
    const int ks2  = tid & 3;           // state slice (interleaved pairs)

    ull St2[16];                        // pair p -> dims of ull idx 4p+ks2
    #pragma unroll
    for (int i = 0; i < 16; i++) St2[i] = 0ull;

    const size_t bs0 = (size_t)b * SEQ;

    for (int c0 = 0; c0 < SEQ; c0 += CT) {
        // ---- load chunk ----
        for (int i = tid; i < CT * 32; i += 256) {
            int t = i >> 5, f = (i & 31) << 2;
            size_t src = ((bs0 + c0 + t) * HKN + kh) * DKD + f;
            cp16(smem_u32(Ks + t * 128 + f), g_k + src);
            cp16(smem_u32(Qs + t * 128 + f), g_q + src);
        }
        for (int i = tid; i < CT * 16; i += 256) {
            int t = i >> 4, f = (i & 15) << 2;
            cp16(smem_u32(Vs + t * 64 + f),
                 g_v + ((bs0 + c0 + t) * HVN + hv) * DVD + half * 64 + f);
        }
        if (tid < CT) {
            cg[tid]  = g_g[(bs0 + c0 + tid) * HVN + hv];
            bet[tid] = g_beta[(bs0 + c0 + tid) * HVN + hv];
        }
        cp_commit();
        cp_wait<0>();
        __syncthreads();

        // ---- transpose K -> Ksj, cumsum ----
        for (int i = tid; i < 8192; i += 256) {
            int r = i >> 7, f = i & 127;
            Ksj[f * KSJ_STRIDE + r] = Ks[r * 128 + f];
        }
        if (tid < 64) {
            float v = cg[tid];
            #pragma unroll
            for (int o = 1; o < 32; o <<= 1) {
                float n = __shfl_up_sync(0xffffffffu, v, o);
                if ((tid & 31) >= o) v += n;
            }
            cg[tid] = v;
        }
        __syncthreads();
        if (tid >= 32 && tid < 64) cg[tid] += cg[31];
        __syncthreads();
        if (tid < 64) gam[tid] = expf(cg[tid]);
        __syncthreads();

        // ---- k.S0 and q.S0 (quad shfl combine; no atomics) ----
        for (int t = 0; t < CT; t++) {
            const ull* kr = (const ull*)(Ks + t * 128);
            const ull* qr = (const ull*)(Qs + t * 128);
            ull ak = 0ull, aq = 0ull;
            #pragma unroll
            for (int p = 0; p < 16; p++) {
                ak = f2fma(kr[4 * p + ks2], St2[p], ak);
                aq = f2fma(qr[4 * p + ks2], St2[p], aq);
            }
            float sk_ = hsum2(ak);
            float sq_ = hsum2(aq);
            sk_ += __shfl_xor_sync(0xffffffffu, sk_, 1);
            sk_ += __shfl_xor_sync(0xffffffffu, sk_, 2);
            sq_ += __shfl_xor_sync(0xffffffffu, sq_, 1);
            sq_ += __shfl_xor_sync(0xffffffffu, sq_, 2);
            if (ks2 == 0) {
                Dl[t * 64 + col2] = sk_;
                Ot[t * 64 + col2] = sq_;
            }
        }
        __syncthreads();

        // ---- rhs transform ----
        for (int i = tid; i < 4096; i += 256) {
            int t = i >> 6;
            float bt = bet[t];
            Dl[i] = bt * Vs[i] - bt * gam[t] * Dl[i];
        }
        __syncthreads();

        // ---- A matrix (strict lower): 4x4 tile, f32x2 over j-pairs ----
        if (jb <= tb) {
            ull acc[4][2];
            #pragma unroll
            for (int a = 0; a < 4; a++) { acc[a][0] = 0ull; acc[a][1] = 0ull; }
            const float* jcol = Ksj + jb * 4;
            #pragma unroll 4
            for (int f = 0; f < 128; f++) {
                const ull* jp = (const ull*)(jcol + f * KSJ_STRIDE);
                ull jv0 = jp[0], jv1 = jp[1];
                #pragma unroll
                for (int a = 0; a < 4; a++) {
                    float tv = Ks[(tb * 4 + a) * 128 + f];
                    ull tv2 = pack2(tv, tv);
                    acc[a][0] = f2fma(tv2, jv0, acc[a][0]);
                    acc[a][1] = f2fma(tv2, jv1, acc[a][1]);
                }
            }
            #pragma unroll
            for (int a = 0; a < 4; a++) {
                int t = tb * 4 + a;
                float bt = bet[t], cgt = cg[t];
                #pragma unroll
                for (int c2 = 0; c2 < 2; c2++) {
                    float lo, hi; unpack2(acc[a][c2], lo, hi);
                    int j0 = jb * 4 + c2 * 2;
                    if (j0 < t)     Am[t * 64 + j0]     = bt * expf(cgt - cg[j0]) * lo;
                    if (j0 + 1 < t) Am[t * 64 + j0 + 1] = bt * expf(cgt - cg[j0 + 1]) * hi;
                }
            }
        }
        __syncthreads();

        // ---- forward substitution: delta = (I+A)^-1 rhs ----
        for (int t = 0; t < CT - 1; t++) {
            float dtc = Dl[t * 64 + col];
            int lo = ks * 16; if (lo <= t) lo = t + 1;
            int hi = ks * 16 + 16;
            for (int tp = lo; tp < hi; tp++)
                Dl[tp * 64 + col] -= Am[tp * 64 + t] * dtc;
            __syncthreads();
        }

        // ---- B matrix (lower incl diag) into Am ----
        if (jb <= tb) {
            ull acc[4][2];
            #pragma unroll
            for (int a = 0; a < 4; a++) { acc[a][0] = 0ull; acc[a][1] = 0ull; }
            const float* jcol = Ksj + jb * 4;
            #pragma unroll 4
            for (int f = 0; f < 128; f++) {
                const ull* jp = (const ull*)(jcol + f * KSJ_STRIDE);
                ull jv0 = jp[0], jv1 = jp[1];
                #pragma unroll
                for (int a = 0; a < 4; a++) {
                    float tv = Qs[(tb * 4 + a) * 128 + f];
                    ull tv2 = pack2(tv, tv);
                    acc[a][0] = f2fma(tv2, jv0, acc[a][0]);
                    acc[a][1] = f2fma(tv2, jv1, acc[a][1]);
                }
            }
            #pragma unroll
            for (int a = 0; a < 4; a++) {
                int t = tb * 4 + a;
                float cgt = cg[t];
                #pragma unroll
                for (int c2 = 0; c2 < 2; c2++) {
                    float lo, hi; unpack2(acc[a][c2], lo, hi);
                    int j0 = jb * 4 + c2 * 2;
                    if (j0 <= t)     Am[t * 64 + j0]     = expf(cgt - cg[j0]) * lo;
                    if (j0 + 1 <= t) Am[t * 64 + j0 + 1] = expf(cgt - cg[j0 + 1]) * hi;
                }
            }
        }
        if (tid < 64) wT[tid] = expf(cg[63] - cg[tid]);
        __syncthreads();

        // ---- outputs (balanced: group ks takes t == ks mod 4) ----
        for (int t = ks; t < CT; t += 4) {
            float o = gam[t] * Ot[t * 64 + col];
            for (int j = 0; j <= t; j++)
                o += Am[t * 64 + j] * Dl[j * 64 + col];
            g_core[((bs0 + c0 + t) * HVN + hv) * DVD + half * 64 + col] = o;
        }

        // ---- state update (interleaved-pair addressing) ----
        {
            const float gT = gam[63];
            const ull gT2 = pack2(gT, gT);
            #pragma unroll
            for (int p = 0; p < 16; p++) St2[p] = f2mul(St2[p], gT2);
            for (int j = 0; j < CT; j++) {
                float cj = wT[j] * Dl[j * 64 + col2];
                ull cj2 = pack2(cj, cj);
                const ull* kj = (const ull*)(Ks + j * 128);
                #pragma unroll
                for (int p = 0; p < 16; p++)
                    St2[p] = f2fma(kj[4 * p + ks2], cj2, St2[p]);
            }
        }
        __syncthreads();
    }
}

// =====================================================================
// RMSNorm * norm_weight * silu(z) -> fp16 core.
// =====================================================================
__global__ __launch_bounds__(128) void rmsnorm_gate_kernel(const float* __restrict__ nw)
{
    const size_t gidx = blockIdx.x;
    const int lane = threadIdx.x;
    const size_t off = gidx * DVD + lane;

    float c = g_core[off];
    float v2 = c * c;
    #pragma unroll
    for (int o = 16; o > 0; o >>= 1)
        v2 += __shfl_xor_sync(0xffffffffu, v2, o);
    __shared__ float red[4];
    if ((lane & 31) == 0) red[lane >> 5] = v2;
    __syncthreads();
    float mean = (red[0] + red[1] + red[2] + red[3]) * (1.0f / 128.0f);

    float z = g_z[off];
    float sz = z / (1.0f + expf(-z));
    float r = c * rsqrtf(mean + 1e-6f) * nw[lane] * sz;
    g_coreh[off] = __float2half_rn(r);
}

// =====================================================================
// launch — fork/join graph (proven).
// =====================================================================
extern "C" void kernel_launch(void* const* d_in, const int* in_sizes, int n_in,
                              void* d_out, int out_size)
{
    const float* X        = (const float*)d_in[0];
    const float* w_qkv    = (const float*)d_in[1];
    const float* w_z      = (const float*)d_in[2];
    const float* w_b      = (const float*)d_in[3];
    const float* w_a      = (const float*)d_in[4];
    const float* w_out    = (const float*)d_in[5];
    const float* conv_w   = (const float*)d_in[6];
    const float* dt_bias  = (const float*)d_in[7];
    const float* A_log    = (const float*)d_in[8];
    const float* norm_w   = (const float*)d_in[9];
    float* out = (float*)d_out;

    float  *p_mixed, *p_z, *p_g, *p_beta;
    __half *p_xh, *p_wqkvh, *p_wzh, *p_wouth, *p_coreh;
    cudaGetSymbolAddress((void**)&p_mixed, g_mixed);
    cudaGetSymbolAddress((void**)&p_z,     g_z);
    cudaGetSymbolAddress((void**)&p_g,     g_g);
    cudaGetSymbolAddress((void**)&p_beta,  g_beta);
    cudaGetSymbolAddress((void**)&p_xh,    g_xh);
    cudaGetSymbolAddress((void**)&p_wqkvh, g_wqkvh);
    cudaGetSymbolAddress((void**)&p_wzh,   g_wzh);
    cudaGetSymbolAddress((void**)&p_wouth, g_wouth);
    cudaGetSymbolAddress((void**)&p_coreh, g_coreh);

    cudaFuncSetAttribute(gemm_fp16, cudaFuncAttributeMaxDynamicSharedMemorySize, GEMM_DYN);
    cudaFuncSetAttribute(scan_kernel, cudaFuncAttributeMaxDynamicSharedMemorySize, SCAN_SMEM);

    int prLow = 0, prHigh = 0;
    cudaDeviceGetStreamPriorityRange(&prLow, &prHigh);
    cudaStream_t s1;
    cudaStreamCreateWithPriority(&s1, cudaStreamNonBlocking, prHigh);
    cudaEvent_t evRoot, evPJ, evG1, evG2;
    cudaEventCreateWithFlags(&evRoot, cudaEventDisableTiming);
    cudaEventCreateWithFlags(&evPJ,   cudaEventDisableTiming);
    cudaEventCreateWithFlags(&evG1,   cudaEventDisableTiming);
    cudaEventCreateWithFlags(&evG2,   cudaEventDisableTiming);

    cudaEventRecord(evRoot, 0);
    cudaStreamWaitEvent(s1, evRoot, 0);

    // [1] round X -> fp16 (s0)
    {
        int n4 = BSTOK * DMODEL / 4;
        round_f16_kernel<<<(n4 + 255) / 256, 256>>>(X, p_xh, n4);
    }
    // [2] transpose w_qkv (s0)
    transpose_f16<<<dim3(CONVD / 32, DMODEL / 32), 256>>>(w_qkv, p_wqkvh, DMODEL, CONVD);
    // [3] gemm1 (s0)
    gemm_fp16<<<dim3(CONVD / 256, BSTOK / 128), 256, GEMM_DYN>>>(
        p_xh, p_wqkvh, p_mixed, BSTOK, CONVD, DMODEL);
    cudaEventRecord(evG1, 0);
    // [4] conv_qk (s0)
    conv_qk_kernel<<<BSTOK, 256>>>(conv_w);

    // s1: off-path preps + proj
    transpose_f16<<<dim3(VDIM / 32, DMODEL / 32), 256, 0, s1>>>(w_z, p_wzh, DMODEL, VDIM);
    transpose_f16<<<dim3(DMODEL / 32, VDIM / 32), 256, 0, s1>>>(w_out, p_wouth, VDIM, DMODEL);
    proj_ba_kernel<<<BSTOK, 256, 0, s1>>>(X, w_b, w_a, dt_bias, A_log, p_beta, p_g);
    cudaEventRecord(evPJ, s1);

    // s1: gemm2
    cudaStreamWaitEvent(s1, evG1, 0);
    gemm_fp16<<<dim3(VDIM / 256, BSTOK / 128), 256, GEMM_DYN, s1>>>(
        p_xh, p_wzh, p_z, BSTOK, VDIM, DMODEL);
    cudaEventRecord(evG2, s1);

    // s0: conv_v -> scan
    conv_v_kernel<<<2048, 256>>>(conv_w);
    cudaStreamWaitEvent(0, evPJ, 0);
    scan_kernel<<<BB * HVN * 2, 256, SCAN_SMEM>>>();

    // join + rmsnorm
    cudaStreamWaitEvent(0, evG2, 0);
    rmsnorm_gate_kernel<<<BSTOK * HVN, 128>>>(norm_w);

    // gemm3
    gemm_fp16<<<dim3(DMODEL / 256, BSTOK / 128), 256, GEMM_DYN>>>(
        p_coreh, p_wouth, out, BSTOK, DMODEL, VDIM);
}

// round 16
// speedup vs baseline: 1.1306x; 1.1306x over previous
#include <cuda_runtime.h>
#include <cuda_fp16.h>
#include <math.h>
#include <stdint.h>

// ---------------- problem constants ----------------
#define BB     2
#define SEQ    2048
#define DMODEL 2048
#define HKN    16
#define HVN    32
#define DKD    128
#define DVD    128
#define KDIM   2048
#define VDIM   4096
#define CONVD  8192
#define BSTOK  (BB*SEQ)
#define CT     64
#define NCH    (SEQ/CT)

// ---------------- scratch ----------------
__device__ float  g_mixed[(size_t)BSTOK * CONVD];
__device__ float  g_z    [(size_t)BSTOK * VDIM];
__device__ float  g_q    [(size_t)BSTOK * KDIM];
__device__ float  g_k    [(size_t)BSTOK * KDIM];
__device__ float  g_v    [(size_t)BSTOK * VDIM];
__device__ float  g_g    [(size_t)BSTOK * HVN];   // raw g
__device__ float  g_beta [(size_t)BSTOK * HVN];
__device__ float  g_core [(size_t)BSTOK * VDIM];
__device__ __half g_xh   [(size_t)BSTOK * DMODEL];
__device__ __half g_wqkvh[(size_t)CONVD * DMODEL];
__device__ __half g_wzh  [(size_t)VDIM * DMODEL];
__device__ __half g_wouth[(size_t)DMODEL * VDIM];
__device__ __half g_coreh[(size_t)BSTOK * VDIM];

// ---------------- ptx helpers ----------------
__device__ __forceinline__ uint32_t smem_u32(const void* p) {
    return (uint32_t)__cvta_generic_to_shared(p);
}
__device__ __forceinline__ void cp16(uint32_t saddr, const void* g) {
    asm volatile("cp.async.cg.shared.global [%0], [%1], 16;\n" :: "r"(saddr), "l"(g));
}
__device__ __forceinline__ void cp_commit() { asm volatile("cp.async.commit_group;\n"); }
template<int N> __device__ __forceinline__ void cp_wait() {
    asm volatile("cp.async.wait_group %0;\n" :: "n"(N));
}
__device__ __forceinline__ void ldsm_x4(uint32_t* r, uint32_t addr) {
    asm volatile("ldmatrix.sync.aligned.m8n8.x4.shared.b16 {%0,%1,%2,%3}, [%4];"
                 : "=r"(r[0]), "=r"(r[1]), "=r"(r[2]), "=r"(r[3]) : "r"(addr));
}
__device__ __forceinline__ void mma16816(float* c, const uint32_t* a, const uint32_t* b) {
    asm volatile(
        "mma.sync.aligned.m16n8k16.row.col.f32.f16.f16.f32 "
        "{%0,%1,%2,%3}, {%4,%5,%6,%7}, {%8,%9}, {%0,%1,%2,%3};"
        : "+f"(c[0]), "+f"(c[1]), "+f"(c[2]), "+f"(c[3])
        : "r"(a[0]), "r"(a[1]), "r"(a[2]), "r"(a[3]), "r"(b[0]), "r"(b[1]));
}
// packed fp32x2
typedef unsigned long long ull;
__device__ __forceinline__ ull f2fma(ull a, ull b, ull c) {
    ull d;
    asm("fma.rn.f32x2 %0, %1, %2, %3;" : "=l"(d) : "l"(a), "l"(b), "l"(c));
    return d;
}
__device__ __forceinline__ ull f2mul(ull a, ull b) {
    ull d;
    asm("mul.rn.f32x2 %0, %1, %2;" : "=l"(d) : "l"(a), "l"(b));
    return d;
}
__device__ __forceinline__ ull pack2(float x, float y) {
    ull r;
    asm("mov.b64 %0, {%1, %2};" : "=l"(r) : "r"(__float_as_uint(x)), "r"(__float_as_uint(y)));
    return r;
}
__device__ __forceinline__ float hsum2(ull v) {
    uint32_t lo, hi;
    asm("mov.b64 {%0, %1}, %2;" : "=r"(lo), "=r"(hi) : "l"(v));
    return __uint_as_float(lo) + __uint_as_float(hi);
}
__device__ __forceinline__ void unpack2(ull v, float& lo, float& hi) {
    uint32_t l, h;
    asm("mov.b64 {%0, %1}, %2;" : "=r"(l), "=r"(h) : "l"(v));
    lo = __uint_as_float(l); hi = __uint_as_float(h);
}

// =====================================================================
// fp16 GEMM (proven, 416 TF/s measured). Do not touch.
// =====================================================================
#define NSTAGE 4
#define A_STAGE_BYTES 16384
#define B_STAGE_BYTES 32768
#define STAGE_BYTES   (A_STAGE_BYTES + B_STAGE_BYTES)
#define GEMM_DYN (NSTAGE*STAGE_BYTES + 1024)

__global__ __launch_bounds__(256, 1) void gemm_fp16(
    const __half* __restrict__ A, const __half* __restrict__ Bt,
    float* __restrict__ C, int M, int N, int K)
{
    extern __shared__ __align__(16) uint8_t dyn[];
    const uint32_t dynb = smem_u32(dyn);
    const uint32_t base = (dynb + 1023u) & ~1023u;

    const int tid  = threadIdx.x;
    const int wid  = tid >> 5;
    const int lane = tid & 31;
    const int bm0 = blockIdx.y * 128;
    const int bn0 = blockIdx.x * 256;
    const int wm  = (wid & 1) * 64;
    const int wn  = (wid >> 1) * 64;
    const int KT  = K >> 6;

    const __half* Arow = A  + (size_t)bm0 * K;
    const __half* Brow = Bt + (size_t)bn0 * K;

    auto load_tile = [&](int buf, int kt) {
        const uint32_t ab = base + buf * STAGE_BYTES;
        const uint32_t bb = ab + A_STAGE_BYTES;
        const int k0 = kt << 6;
        #pragma unroll
        for (int t = 0; t < 4; t++) {
            int c = tid + t * 256;
            int row = c >> 3;
            int cb  = (c & 7) << 4;
            uint32_t off = (uint32_t)(row * 128 + cb);
            uint32_t sw = off ^ ((off >> 3) & 0x70u);
            cp16(ab + sw, Arow + (size_t)row * K + k0 + (cb >> 1));
        }
        #pragma unroll
        for (int t = 0; t < 8; t++) {
            int c = tid + t * 256;
            int row = c >> 3;
            int cb  = (c & 7) << 4;
            uint32_t off = (uint32_t)(row * 128 + cb);
            uint32_t sw = off ^ ((off >> 3) & 0x70u);
            cp16(bb + sw, Brow + (size_t)row * K + k0 + (cb >> 1));
        }
        cp_commit();
    };

    const int aRowL = lane & 15;
    const int aKH2  = (lane >> 4) * 16;
    const int bRowL = ((lane >> 4) & 1) * 8 + (lane & 7);
    const int bKH2  = ((lane >> 3) & 1) * 16;

    float acc[4][8][4];
    #pragma unroll
    for (int i = 0; i < 4; i++)
        #pragma unroll
        for (int j = 0; j < 8; j++)
            #pragma unroll
            for (int q = 0; q < 4; q++) acc[i][j][q] = 0.0f;

    load_tile(0, 0);
    load_tile(1, KT > 1 ? 1 : 0);
    load_tile(2, KT > 2 ? 2 : 0);

    for (int i = 0; i < KT; i++) {
        cp_wait<2>();
        __syncthreads();

        if (i + 3 < KT) load_tile((i + 3) % NSTAGE, i + 3);
        else            cp_commit();

        const uint32_t ab = base + (i % NSTAGE) * STAGE_BYTES;
        const uint32_t bb = ab + A_STAGE_BYTES;

        #pragma unroll
        for (int ks = 0; ks < 4; ks++) {
            uint32_t af[4][4];
            uint32_t bf[4][4];
            #pragma unroll
            for (int mi = 0; mi < 4; mi++) {
                int row = wm + mi * 16 + aRowL;
                uint32_t cb = (uint32_t)((ks * 32 + aKH2) ^ ((row & 7) << 4));
                ldsm_x4(af[mi], ab + row * 128 + cb);
            }
            #pragma unroll
            for (int ni2 = 0; ni2 < 4; ni2++) {
                int row = wn + ni2 * 16 + bRowL;
                uint32_t cb = (uint32_t)((ks * 32 + bKH2) ^ ((row & 7) << 4));
                ldsm_x4(bf[ni2], bb + row * 128 + cb);
            }
            #pragma unroll
            for (int mi = 0; mi < 4; mi++)
                #pragma unroll
                for (int ni = 0; ni < 8; ni++)
                    mma16816(acc[mi][ni], af[mi], &bf[ni >> 1][(ni & 1) * 2]);
        }
    }

    const int l4 = lane >> 2;
    const int l2 = (lane & 3) * 2;
    #pragma unroll
    for (int mi = 0; mi < 4; mi++) {
        #pragma unroll
        for (int ni = 0; ni < 8; ni++) {
            float* c = acc[mi][ni];
            size_t r = (size_t)(bm0 + wm + mi * 16 + l4) * N + bn0 + wn + ni * 8 + l2;
            *(float2*)(C + r)                 = make_float2(c[0], c[1]);
            *(float2*)(C + r + 8 * (size_t)N) = make_float2(c[2], c[3]);
        }
    }
}

// =====================================================================
// prep kernels
// =====================================================================
__global__ __launch_bounds__(256) void round_f16_kernel(
    const float* __restrict__ src, __half* __restrict__ dst, int n4)
{
    int i = blockIdx.x * 256 + threadIdx.x;
    if (i < n4) {
        float4 v = ((const float4*)src)[i];
        ((__half2*)dst)[i * 2]     = __floats2half2_rn(v.x, v.y);
        ((__half2*)dst)[i * 2 + 1] = __floats2half2_rn(v.z, v.w);
    }
}

__global__ __launch_bounds__(256) void transpose_f16(
    const float* __restrict__ src, __half* __restrict__ dst, int K, int N)
{
    __shared__ float tile[32][33];
    const int n0 = blockIdx.x * 32, k0 = blockIdx.y * 32;
    const int tx = threadIdx.x & 31, ty = threadIdx.x >> 5;
    #pragma unroll
    for (int j = 0; j < 32; j += 8)
        tile[ty + j][tx] = src[(size_t)(k0 + ty + j) * N + n0 + tx];
    __syncthreads();
    #pragma unroll
    for (int j = 0; j < 32; j += 8)
        dst[(size_t)(n0 + ty + j) * K + k0 + tx] = __float2half_rn(tile[tx][ty + j]);
}

// =====================================================================
// b/a projections -> beta, g (raw log-decay)
// =====================================================================
__global__ __launch_bounds__(256) void proj_ba_kernel(
    const float* __restrict__ X, const float* __restrict__ wb,
    const float* __restrict__ wa, const float* __restrict__ dt_bias,
    const float* __restrict__ A_log,
    float* __restrict__ beta, float* __restrict__ gout)
{
    __shared__ float xs[DMODEL];
    const int bs = blockIdx.x;
    const int tid = threadIdx.x;
    for (int t = tid; t < DMODEL; t += 256)
        xs[t] = X[(size_t)bs * DMODEL + t];
    __syncthreads();

    const int out  = tid >> 2;
    const int part = tid & 3;
    const bool is_b = (out < 32);
    const int h = is_b ? out : out - 32;
    const float* w = (is_b ? wb : wa) + h;

    float acc = 0.0f;
    #pragma unroll 8
    for (int d = part; d < DMODEL; d += 4)
        acc += xs[d] * w[d * 32];
    acc += __shfl_xor_sync(0xffffffffu, acc, 1);
    acc += __shfl_xor_sync(0xffffffffu, acc, 2);

    if (part == 0) {
        if (is_b) {
            beta[(size_t)bs * HVN + h] = 1.0f / (1.0f + expf(-acc));
        } else {
            float x = acc + dt_bias[h];
            float sp = (x > 20.0f) ? x : log1pf(expf(x));
            gout[(size_t)bs * HVN + h] = -expf(A_log[h]) * sp;
        }
    }
}

// =====================================================================
// conv1d(K=4) + silu + per-head l2norm for q,k. One CTA per token.
// =====================================================================
__global__ __launch_bounds__(256) void conv_qk_kernel(const float* __restrict__ conv_w)
{
    const int bs   = blockIdx.x;
    const int s    = bs % SEQ;
    const long bsl = bs;
    const int half = threadIdx.x >> 7;
    const int lane = threadIdx.x & 127;
    __shared__ float red[2][4];

    #pragma unroll 1
    for (int it = 0; it < 16; it++) {
        const int hy = it * 2 + half;
        const bool is_k = (hy >= HKN);
        const int head  = is_k ? hy - HKN : hy;
        const int c     = (is_k ? KDIM : 0) + head * DKD + lane;

        const float4 w4 = *(const float4*)(conv_w + c * 4);

        float acc = w4.w * g_mixed[bsl * CONVD + c];
        if (s > 0) acc += w4.z * g_mixed[(bsl - 1) * CONVD + c];
        if (s > 1) acc += w4.y * g_mixed[(bsl - 2) * CONVD + c];
        if (s > 2) acc += w4.x * g_mixed[(bsl - 3) * CONVD + c];

        float val = acc / (1.0f + expf(-acc));

        float ss2 = val * val;
        #pragma unroll
        for (int o = 16; o > 0; o >>= 1)
            ss2 += __shfl_xor_sync(0xffffffffu, ss2, o);
        if ((lane & 31) == 0) red[half][lane >> 5] = ss2;
        __syncthreads();
        float tot = red[half][0] + red[half][1] + red[half][2] + red[half][3];

        float outv = val * rsqrtf(tot + 1e-6f);
        if (!is_k) outv *= 0.08838834764831845f;

        float* dst = is_k ? g_k : g_q;
        dst[(size_t)bs * KDIM + head * DKD + lane] = outv;
        __syncthreads();
    }
}

// =====================================================================
// conv1d + silu for v. Grid-stride, 2048 CTAs.
// =====================================================================
__global__ __launch_bounds__(256) void conv_v_kernel(const float* __restrict__ conv_w)
{
    const size_t total = (size_t)BSTOK * VDIM;
    for (size_t idx = (size_t)blockIdx.x * 256 + threadIdx.x; idx < total;
         idx += (size_t)gridDim.x * 256) {
        const int cv = (int)(idx % VDIM);
        const long bsl = (long)(idx / VDIM);
        const int s = (int)(bsl % SEQ);
        const int c = 2 * KDIM + cv;

        const float4 w4 = *(const float4*)(conv_w + c * 4);

        float acc = w4.w * g_mixed[bsl * CONVD + c];
        if (s > 0) acc += w4.z * g_mixed[(bsl - 1) * CONVD + c];
        if (s > 1) acc += w4.y * g_mixed[(bsl - 2) * CONVD + c];
        if (s > 2) acc += w4.x * g_mixed[(bsl - 3) * CONVD + c];

        g_v[idx] = acc / (1.0f + expf(-acc));
    }
}

// =====================================================================
// CHUNKED gated delta-rule scan (WY form) — r14 base, atomic-free dots.
// k.S0/q.S0 slice partials go to 4 scratch smem buffers, then one
// vectorized combine pass (no ATOMS, no shfl chains). Transpose of K
// into Ksj happens AFTER the dot passes (Ksj doubles as scratch).
// Output loop balanced: group ks takes t == ks (mod 4).
// =====================================================================
#define KSJ_STRIDE 66
#define SCAN_SMEM_FLOATS (8192 + 8192 + 128*KSJ_STRIDE + 4096*5 + 256)
#define SCAN_SMEM (SCAN_SMEM_FLOATS * 4)   // 182272 bytes

__global__ __launch_bounds__(256, 1) void scan_kernel()
{
    extern __shared__ __align__(16) float sm[];
    float* Ks  = sm;                       // [64][128]
    float* Qs  = Ks + 8192;                // [64][128]
    float* Ksj = Qs + 8192;                // [128][66] (scratch, then K^T)
    float* Vs  = Ksj + 128 * KSJ_STRIDE;   // [64][64]
    float* Am  = Vs + 4096;                // [64][64] A, later B
    float* Bs  = Am + 4096;                // [64][64] scratch
    float* Dl  = Bs + 4096;                // [64][64] rhs -> delta
    float* Ot  = Dl + 4096;                // [64][64] q.S0
    float* cg  = Ot + 4096;                // [64]
    float* bet = cg + 64;
    float* gam = bet + 64;
    float* wT  = gam + 64;

    const int blk  = blockIdx.x;
    const int half = blk & 1;
    const int hv   = (blk >> 1) & (HVN - 1);
    const int b    = blk >> 6;
    const int kh   = hv >> 1;
    const int tid  = threadIdx.x;
    const int col  = tid & 63;
    const int ks   = tid >> 6;          // 0..3
    const int tb   = tid >> 4;          // A/B tile row
    const int jb   = tid & 15;          // A/B tile col

    ull St2[16];                        // slice ks owns dims [ks*32, ks*32+32)
    #pragma unroll
    for (int i = 0; i < 16; i++) St2[i] = 0ull;

    const size_t bs0 = (size_t)b * SEQ;

    for (int c0 = 0; c0 < SEQ; c0 += CT) {
        // ---- load chunk ----
        for (int i = tid; i < CT * 32; i += 256) {
            int t = i >> 5, f = (i & 31) << 2;
            size_t src = ((bs0 + c0 + t) * HKN + kh) * DKD + f;
            cp16(smem_u32(Ks + t * 128 + f), g_k + src);
            cp16(smem_u32(Qs + t * 128 + f), g_q + src);
        }
        for (int i = tid; i < CT * 16; i += 256) {
            int t = i >> 4, f = (i & 15) << 2;
            cp16(smem_u32(Vs + t * 64 + f),
                 g_v + ((bs0 + c0 + t) * HVN + hv) * DVD + half * 64 + f);
        }
        if (tid < CT) {
            cg[tid]  = g_g[(bs0 + c0 + tid) * HVN + hv];
            bet[tid] = g_beta[(bs0 + c0 + tid) * HVN + hv];
        }
        cp_commit();
        cp_wait<0>();
        __syncthreads();

        // ---- cumsum + gamma ----
        if (tid < 64) {
            float v = cg[tid];
            #pragma unroll
            for (int o = 1; o < 32; o <<= 1) {
                float n = __shfl_up_sync(0xffffffffu, v, o);
                if ((tid & 31) >= o) v += n;
            }
            cg[tid] = v;
        }
        __syncthreads();
        if (tid >= 32 && tid < 64) cg[tid] += cg[31];
        __syncthreads();
        if (tid < 64) gam[tid] = expf(cg[tid]);
        __syncthreads();

        // ---- k.S0: slice partials into scratch, combine into Dl ----
        {
            float* kb = (ks == 0) ? Ot : (ks == 1) ? Am : (ks == 2) ? Bs : Ksj;
            for (int t = 0; t < CT; t++) {
                const ull* kr = (const ull*)(Ks + t * 128 + ks * 32);
                ull ak = 0ull;
                #pragma unroll
                for (int p = 0; p < 16; p++) ak = f2fma(kr[p], St2[p], ak);
                kb[t * 64 + col] = hsum2(ak);
            }
        }
        __syncthreads();
        for (int i = tid; i < 4096; i += 256)
            Dl[i] = (Ot[i] + Am[i]) + (Bs[i] + Ksj[i]);
        __syncthreads();

        // ---- q.S0: slice partials, combine into Ot ----
        {
            float* qb = (ks == 0) ? Am : (ks == 1) ? Bs : (ks == 2) ? Ksj : (Ksj + 4096);
            for (int t = 0; t < CT; t++) {
                const ull* qr = (const ull*)(Qs + t * 128 + ks * 32);
                ull aq = 0ull;
                #pragma unroll
                for (int p = 0; p < 16; p++) aq = f2fma(qr[p], St2[p], aq);
                qb[t * 64 + col] = hsum2(aq);
            }
        }
        __syncthreads();
        for (int i = tid; i < 4096; i += 256)
            Ot[i] = (Am[i] + Bs[i]) + (Ksj[i] + Ksj[4096 + i]);
        __syncthreads();

        // ---- transpose K -> Ksj (scratch now free) ----
        for (int i = tid; i < 8192; i += 256) {
            int r = i >> 7, f = i & 127;
            Ksj[f * KSJ_STRIDE + r] = Ks[r * 128 + f];
        }
        __syncthreads();

        // ---- rhs transform ----
        for (int i = tid; i < 4096; i += 256) {
            int t = i >> 6;
            float bt = bet[t];
            Dl[i] = bt * Vs[i] - bt * gam[t] * Dl[i];
        }
        __syncthreads();

        // ---- A matrix (strict lower): 4x4 tile, f32x2 over j-pairs ----
        if (jb <= tb) {
            ull acc[4][2];
            #pragma unroll
            for (int a = 0; a < 4; a++) { acc[a][0] = 0ull; acc[a][1] = 0ull; }
            const float* jcol = Ksj + jb * 4;
            #pragma unroll 4
            for (int f = 0; f < 128; f++) {
                const ull* jp = (const ull*)(jcol + f * KSJ_STRIDE);
                ull jv0 = jp[0], jv1 = jp[1];
                #pragma unroll
                for (int a = 0; a < 4; a++) {
                    float tv = Ks[(tb * 4 + a) * 128 + f];
                    ull tv2 = pack2(tv, tv);
                    acc[a][0] = f2fma(tv2, jv0, acc[a][0]);
                    acc[a][1] = f2fma(tv2, jv1, acc[a][1]);
                }
            }
            #pragma unroll
            for (int a = 0; a < 4; a++) {
                int t = tb * 4 + a;
                float bt = bet[t], cgt = cg[t];
                #pragma unroll
                for (int c2 = 0; c2 < 2; c2++) {
                    float lo, hi; unpack2(acc[a][c2], lo, hi);
                    int j0 = jb * 4 + c2 * 2;
                    if (j0 < t)     Am[t * 64 + j0]     = bt * expf(cgt - cg[j0]) * lo;
                    if (j0 + 1 < t) Am[t * 64 + j0 + 1] = bt * expf(cgt - cg[j0 + 1]) * hi;
                }
            }
        }
        __syncthreads();

        // ---- forward substitution: delta = (I+A)^-1 rhs ----
        for (int t = 0; t < CT - 1; t++) {
            float dtc = Dl[t * 64 + col];
            int lo = ks * 16; if (lo <= t) lo = t + 1;
            int hi = ks * 16 + 16;
            for (int tp = lo; tp < hi; tp++)
                Dl[tp * 64 + col] -= Am[tp * 64 + t] * dtc;
            __syncthreads();
        }

        // ---- B matrix (lower incl diag) into Am ----
        if (jb <= tb) {
            ull acc[4][2];
            #pragma unroll
            for (int a = 0; a < 4; a++) { acc[a][0] = 0ull; acc[a][1] = 0ull; }
            const float* jcol = Ksj + jb * 4;
            #pragma unroll 4
            for (int f = 0; f < 128; f++) {
                const ull* jp = (const ull*)(jcol + f * KSJ_STRIDE);
                ull jv0 = jp[0], jv1 = jp[1];
                #pragma unroll
                for (int a = 0; a < 4; a++) {
                    float tv = Qs[(tb * 4 + a) * 128 + f];
                    ull tv2 = pack2(tv, tv);
                    acc[a][0] = f2fma(tv2, jv0, acc[a][0]);
                    acc[a][1] = f2fma(tv2, jv1, acc[a][1]);
                }
            }
            #pragma unroll
            for (int a = 0; a < 4; a++) {
                int t = tb * 4 + a;
                float cgt = cg[t];
                #pragma unroll
                for (int c2 = 0; c2 < 2; c2++) {
                    float lo, hi; unpack2(acc[a][c2], lo, hi);
                    int j0 = jb * 4 + c2 * 2;
                    if (j0 <= t)     Am[t * 64 + j0]     = expf(cgt - cg[j0]) * lo;
                    if (j0 + 1 <= t) Am[t * 64 + j0 + 1] = expf(cgt - cg[j0 + 1]) * hi;
                }
            }
        }
        if (tid < 64) wT[tid] = expf(cg[63] - cg[tid]);
        __syncthreads();

        // ---- outputs (balanced: group ks takes t == ks mod 4) ----
        for (int t = ks; t < CT; t += 4) {
            float o = gam[t] * Ot[t * 64 + col];
            for (int j = 0; j <= t; j++)
                o += Am[t * 64 + j] * Dl[j * 64 + col];
            g_core[((bs0 + c0 + t) * HVN + hv) * DVD + half * 64 + col] = o;
        }

        // ---- state update ----
        {
            const float gT = gam[63];
            const ull gT2 = pack2(gT, gT);
            #pragma unroll
            for (int p = 0; p < 16; p++) St2[p] = f2mul(St2[p], gT2);
            for (int j = 0; j < CT; j++) {
                float cj = wT[j] * Dl[j * 64 + col];
                ull cj2 = pack2(cj, cj);
                const ull* kj = (const ull*)(Ks + j * 128 + ks * 32);
                #pragma unroll
                for (int p = 0; p < 16; p++) St2[p] = f2fma(kj[p], cj2, St2[p]);
            }
        }
        __syncthreads();
    }
}

// =====================================================================
// RMSNorm * norm_weight * silu(z) -> fp16 core.
// =====================================================================
__global__ __launch_bounds__(128) void rmsnorm_gate_kernel(const float* __restrict__ nw)
{
    const size_t gidx = blockIdx.x;
    const int lane = threadIdx.x;
    const size_t off = gidx * DVD + lane;

    float c = g_core[off];
    float v2 = c * c;
    #pragma unroll
    for (int o = 16; o > 0; o >>= 1)
        v2 += __shfl_xor_sync(0xffffffffu, v2, o);
    __shared__ float red[4];
    if ((lane & 31) == 0) red[lane >> 5] = v2;
    __syncthreads();
    float mean = (red[0] + red[1] + red[2] + red[3]) * (1.0f / 128.0f);

    float z = g_z[off];
    float sz = z / (1.0f + expf(-z));
    float r = c * rsqrtf(mean + 1e-6f) * nw[lane] * sz;
    g_coreh[off] = __float2half_rn(r);
}

// =====================================================================
// launch — fork/join graph (proven).
// =====================================================================
extern "C" void kernel_launch(void* const* d_in, const int* in_sizes, int n_in,
                              void* d_out, int out_size)
{
    const float* X        = (const float*)d_in[0];
    const float* w_qkv    = (const float*)d_in[1];
    const float* w_z      = (const float*)d_in[2];
    const float* w_b      = (const float*)d_in[3];
    const float* w_a      = (const float*)d_in[4];
    const float* w_out    = (const float*)d_in[5];
    const float* conv_w   = (const float*)d_in[6];
    const float* dt_bias  = (const float*)d_in[7];
    const float* A_log    = (const float*)d_in[8];
    const float* norm_w   = (const float*)d_in[9];
    float* out = (float*)d_out;

    float  *p_mixed, *p_z, *p_g, *p_beta;
    __half *p_xh, *p_wqkvh, *p_wzh, *p_wouth, *p_coreh;
    cudaGetSymbolAddress((void**)&p_mixed, g_mixed);
    cudaGetSymbolAddress((void**)&p_z,     g_z);
    cudaGetSymbolAddress((void**)&p_g,     g_g);
    cudaGetSymbolAddress((void**)&p_beta,  g_beta);
    cudaGetSymbolAddress((void**)&p_xh,    g_xh);
    cudaGetSymbolAddress((void**)&p_wqkvh, g_wqkvh);
    cudaGetSymbolAddress((void**)&p_wzh,   g_wzh);
    cudaGetSymbolAddress((void**)&p_wouth, g_wouth);
    cudaGetSymbolAddress((void**)&p_coreh, g_coreh);

    cudaFuncSetAttribute(gemm_fp16, cudaFuncAttributeMaxDynamicSharedMemorySize, GEMM_DYN);
    cudaFuncSetAttribute(scan_kernel, cudaFuncAttributeMaxDynamicSharedMemorySize, SCAN_SMEM);

    int prLow = 0, prHigh = 0;
    cudaDeviceGetStreamPriorityRange(&prLow, &prHigh);
    cudaStream_t s1;
    cudaStreamCreateWithPriority(&s1, cudaStreamNonBlocking, prHigh);
    cudaEvent_t evRoot, evPJ, evG1, evG2;
    cudaEventCreateWithFlags(&evRoot, cudaEventDisableTiming);
    cudaEventCreateWithFlags(&evPJ,   cudaEventDisableTiming);
    cudaEventCreateWithFlags(&evG1,   cudaEventDisableTiming);
    cudaEventCreateWithFlags(&evG2,   cudaEventDisableTiming);

    cudaEventRecord(evRoot, 0);
    cudaStreamWaitEvent(s1, evRoot, 0);

    // [1] round X -> fp16 (s0)
    {
        int n4 = BSTOK * DMODEL / 4;
        round_f16_kernel<<<(n4 + 255) / 256, 256>>>(X, p_xh, n4);
    }
    // [2] transpose w_qkv (s0)
    transpose_f16<<<dim3(CONVD / 32, DMODEL / 32), 256>>>(w_qkv, p_wqkvh, DMODEL, CONVD);
    // [3] gemm1 (s0)
    gemm_fp16<<<dim3(CONVD / 256, BSTOK / 128), 256, GEMM_DYN>>>(
        p_xh, p_wqkvh, p_mixed, BSTOK, CONVD, DMODEL);
    cudaEventRecord(evG1, 0);
    // [4] conv_qk (s0)
    conv_qk_kernel<<<BSTOK, 256>>>(conv_w);

    // s1: off-path preps + proj
    transpose_f16<<<dim3(VDIM / 32, DMODEL / 32), 256, 0, s1>>>(w_z, p_wzh, DMODEL, VDIM);
    transpose_f16<<<dim3(DMODEL / 32, VDIM / 32), 256, 0, s1>>>(w_out, p_wouth, VDIM, DMODEL);
    proj_ba_kernel<<<BSTOK, 256, 0, s1>>>(X, w_b, w_a, dt_bias, A_log, p_beta, p_g);
    cudaEventRecord(evPJ, s1);

    // s1: gemm2
    cudaStreamWaitEvent(s1, evG1, 0);
    gemm_fp16<<<dim3(VDIM / 256, BSTOK / 128), 256, GEMM_DYN, s1>>>(
        p_xh, p_wzh, p_z, BSTOK, VDIM, DMODEL);
    cudaEventRecord(evG2, s1);

    // s0: conv_v -> scan
    conv_v_kernel<<<2048, 256>>>(conv_w);
    cudaStreamWaitEvent(0, evPJ, 0);
    scan_kernel<<<BB * HVN * 2, 256, SCAN_SMEM>>>();

    // join + rmsnorm
    cudaStreamWaitEvent(0, evG2, 0);
    rmsnorm_gate_kernel<<<BSTOK * HVN, 128>>>(norm_w);

    // gemm3
    gemm_fp16<<<dim3(DMODEL / 256, BSTOK / 128), 256, GEMM_DYN>>>(
        p_coreh, p_wouth, out, BSTOK, DMODEL, VDIM);
}